// round 1
// baseline (speedup 1.0000x reference)
#include <cuda_runtime.h>
#include <math.h>

// Problem constants
#define N    8192
#define D_O  512
#define D_T  768

// GEMM tiling
#define BM 128
#define BN 128
#define BK 8
#define NBJ (N / BN)   // 64 column-blocks

// ---------------------------------------------------------------------------
// Scratch (static __device__ arrays: allowed; no cudaMalloc anywhere)
// ---------------------------------------------------------------------------
__device__ float g_xn[N * D_O];                 // 16 MB normalized model_output
__device__ float g_tn[N * D_T];                 // 24 MB normalized targets
__device__ float g_sim_o[(long long)N * N];     // 256 MB
__device__ float g_sim_t[(long long)N * N];     // 256 MB
__device__ float g_dpart[2][N * NBJ];           // per-(row, jblock) exp partial sums
__device__ float g_logden[2][N];                // log of row denominators
__device__ float g_losspart[2 * N];             // per-block loss partials

// ---------------------------------------------------------------------------
// Row L2-normalize: one block per row
// ---------------------------------------------------------------------------
__global__ void normalize_kernel(const float* __restrict__ x, int D, int which) {
    float* out = (which == 0) ? g_xn : g_tn;
    int row = blockIdx.x;
    const float* xr = x + (long long)row * D;

    float ss = 0.f;
    for (int c = threadIdx.x; c < D; c += 256) {
        float v = xr[c];
        ss += v * v;
    }
    #pragma unroll
    for (int o = 16; o; o >>= 1) ss += __shfl_xor_sync(0xffffffffu, ss, o);

    __shared__ float sw[8];
    __shared__ float sscale;
    if ((threadIdx.x & 31) == 0) sw[threadIdx.x >> 5] = ss;
    __syncthreads();
    if (threadIdx.x == 0) {
        float t = 0.f;
        #pragma unroll
        for (int w = 0; w < 8; w++) t += sw[w];
        sscale = 1.0f / fmaxf(sqrtf(t), 1e-8f);
    }
    __syncthreads();

    float s = sscale;
    float* orow = out + (long long)row * D;
    for (int c = threadIdx.x; c < D; c += 256) orow[c] = xr[c] * s;
}

// ---------------------------------------------------------------------------
// Fused GEMM: sim = A @ A^T, store sim tile, and accumulate deterministic
// per-(row, jblock) partial sums of exp(sim) with the diagonal excluded.
// 128x128 C-tile, 256 threads, 8x8 micro-tile per thread, BK=8.
// ---------------------------------------------------------------------------
template <int WHICH>
__global__ void __launch_bounds__(256) gemm_simexp_kernel() {
    constexpr int D = (WHICH == 0) ? D_O : D_T;
    const float* A   = (WHICH == 0) ? g_xn : g_tn;
    float* sim       = (WHICH == 0) ? g_sim_o : g_sim_t;
    float* dpart     = g_dpart[WHICH];

    __shared__ float As[BK][BM];
    __shared__ float Bs[BK][BN];
    __shared__ float spart[BM][17];   // padded: conflict-free column reduce

    const int tid = threadIdx.x;
    const int tx = tid & 15;          // 16 cols of threads
    const int ty = tid >> 4;          // 16 rows of threads
    const int bi = blockIdx.y;
    const int bj = blockIdx.x;

    const float* Ab = A + (long long)bi * BM * D;
    const float* Bb = A + (long long)bj * BN * D;

    // Global->SMEM load mapping: each thread loads one float4 per tile
    const int lrow = tid >> 1;
    const int lcol = (tid & 1) * 4;

    float acc[8][8];
    #pragma unroll
    for (int i = 0; i < 8; i++)
        #pragma unroll
        for (int j = 0; j < 8; j++) acc[i][j] = 0.f;

    for (int k0 = 0; k0 < D; k0 += BK) {
        float4 a4 = *(const float4*)(Ab + (long long)lrow * D + k0 + lcol);
        float4 b4 = *(const float4*)(Bb + (long long)lrow * D + k0 + lcol);
        __syncthreads();
        As[lcol + 0][lrow] = a4.x; As[lcol + 1][lrow] = a4.y;
        As[lcol + 2][lrow] = a4.z; As[lcol + 3][lrow] = a4.w;
        Bs[lcol + 0][lrow] = b4.x; Bs[lcol + 1][lrow] = b4.y;
        Bs[lcol + 2][lrow] = b4.z; Bs[lcol + 3][lrow] = b4.w;
        __syncthreads();

        #pragma unroll
        for (int k = 0; k < BK; k++) {
            float a[8], b[8];
            *(float4*)(a)     = *(const float4*)(&As[k][ty * 8]);
            *(float4*)(a + 4) = *(const float4*)(&As[k][ty * 8 + 4]);
            *(float4*)(b)     = *(const float4*)(&Bs[k][tx * 8]);
            *(float4*)(b + 4) = *(const float4*)(&Bs[k][tx * 8 + 4]);
            #pragma unroll
            for (int i = 0; i < 8; i++)
                #pragma unroll
                for (int j = 0; j < 8; j++)
                    acc[i][j] = fmaf(a[i], b[j], acc[i][j]);
        }
    }

    // Epilogue: store sims, accumulate exp row-sums (diag excluded)
    const int gi0 = bi * BM + ty * 8;
    const int gj0 = bj * BN + tx * 8;
    #pragma unroll
    for (int i = 0; i < 8; i++) {
        const int gi = gi0 + i;
        float rs = 0.f;
        #pragma unroll
        for (int j = 0; j < 8; j++) {
            if (gi != gj0 + j) rs += expf(acc[i][j]);
        }
        float* simrow = sim + (long long)gi * N + gj0;
        *(float4*)(simrow)     = make_float4(acc[i][0], acc[i][1], acc[i][2], acc[i][3]);
        *(float4*)(simrow + 4) = make_float4(acc[i][4], acc[i][5], acc[i][6], acc[i][7]);
        spart[ty * 8 + i][tx] = rs;
    }
    __syncthreads();

    if (tid < BM) {
        float t = 0.f;
        #pragma unroll
        for (int x = 0; x < 16; x++) t += spart[tid][x];
        dpart[(bi * BM + tid) * NBJ + bj] = t;
    }
}

// ---------------------------------------------------------------------------
// Per-row log-denominator: reduce 64 block-partials, take log. One block/row.
// ---------------------------------------------------------------------------
__global__ void logdenom_kernel(int which) {
    const float* dpart = g_dpart[which];
    float* ld = g_logden[which];
    int row = blockIdx.x;
    float v = dpart[row * NBJ + threadIdx.x];   // 64 threads
    #pragma unroll
    for (int o = 16; o; o >>= 1) v += __shfl_xor_sync(0xffffffffu, v, o);
    __shared__ float sw[2];
    if ((threadIdx.x & 31) == 0) sw[threadIdx.x >> 5] = v;
    __syncthreads();
    if (threadIdx.x == 0) ld[row] = logf(sw[0] + sw[1]);
}

// ---------------------------------------------------------------------------
// Loss pass: each block handles half a row (4096 j's); deterministic reduce.
// term = tp^3 * ((sim_t - Lt) - (sim_o - Lo)),  tp = exp(sim_t - Lt)
// ---------------------------------------------------------------------------
__global__ void loss_kernel() {
    const int b  = blockIdx.x;
    const int i  = b >> 1;
    const int j0 = (b & 1) * (N / 2);
    const float Lo = g_logden[0][i];
    const float Lt = g_logden[1][i];
    const float* so = g_sim_o + (long long)i * N + j0;
    const float* st = g_sim_t + (long long)i * N + j0;

    float acc = 0.f;
    for (int k = threadIdx.x; k < N / 2; k += 256) {
        if (j0 + k == i) continue;   // diagonal: teacher prob underflows to 0
        float s_t = st[k];
        float s_o = so[k];
        float ltp = s_t - Lt;
        float tp  = expf(ltp);
        acc += tp * tp * tp * (ltp - (s_o - Lo));
    }
    #pragma unroll
    for (int o = 16; o; o >>= 1) acc += __shfl_xor_sync(0xffffffffu, acc, o);
    __shared__ float sw[8];
    if ((threadIdx.x & 31) == 0) sw[threadIdx.x >> 5] = acc;
    __syncthreads();
    if (threadIdx.x == 0) {
        float t = 0.f;
        #pragma unroll
        for (int w = 0; w < 8; w++) t += sw[w];
        g_losspart[b] = t;
    }
}

// ---------------------------------------------------------------------------
// Final deterministic reduction of 16384 partials -> scalar mean
// ---------------------------------------------------------------------------
__global__ void final_kernel(float* out) {
    float acc = 0.f;
    for (int k = threadIdx.x; k < 2 * N; k += 256) acc += g_losspart[k];
    #pragma unroll
    for (int o = 16; o; o >>= 1) acc += __shfl_xor_sync(0xffffffffu, acc, o);
    __shared__ float sw[8];
    if ((threadIdx.x & 31) == 0) sw[threadIdx.x >> 5] = acc;
    __syncthreads();
    if (threadIdx.x == 0) {
        float t = 0.f;
        #pragma unroll
        for (int w = 0; w < 8; w++) t += sw[w];
        out[0] = t * (1.0f / ((float)N * (float)N));
    }
}

// ---------------------------------------------------------------------------
// Launch (graph-capturable: kernel launches only, single stream)
// ---------------------------------------------------------------------------
extern "C" void kernel_launch(void* const* d_in, const int* in_sizes, int n_in,
                              void* d_out, int out_size) {
    const float* mo = (const float*)d_in[0];   // model_output [8192, 512]
    const float* tg = (const float*)d_in[1];   // targets      [8192, 768]
    float* out = (float*)d_out;

    normalize_kernel<<<N, 256>>>(mo, D_O, 0);
    normalize_kernel<<<N, 256>>>(tg, D_T, 1);

    dim3 grid(NBJ, N / BM);  // 64 x 64 blocks
    gemm_simexp_kernel<0><<<grid, 256>>>();
    gemm_simexp_kernel<1><<<grid, 256>>>();

    logdenom_kernel<<<N, 64>>>(0);
    logdenom_kernel<<<N, 64>>>(1);

    loss_kernel<<<2 * N, 256>>>();
    final_kernel<<<1, 256>>>(out);
}

// round 3
// speedup vs baseline: 7.1746x; 7.1746x over previous
#include <cuda_runtime.h>
#include <cuda_bf16.h>
#include <math.h>
#include <stdint.h>

// Problem constants
#define N    8192
#define D_O  512
#define D_T  768

#define BM 128
#define BN 128
#define NBJ (N / BN)   // 64 column-blocks

// Arch-specific (sm_103a) feature gate: tcgen05 PTX only legal at compute_103a.
#if defined(__CUDA_ARCH__) && defined(__CUDA_ARCH_FEAT_SM103_ALL)
#define USE_TCGEN05 1
#else
#define USE_TCGEN05 0
#endif

#define SMEM_SWIZZLE_128B(b) ((b) ^ (((b) >> 3) & 0x70))

// ---------------------------------------------------------------------------
// Common helpers
// ---------------------------------------------------------------------------
__device__ __forceinline__ uint32_t smem_to_u32(const void* p) {
    uint32_t a;
    asm("{ .reg .u64 t; cvta.to.shared.u64 t, %1; cvt.u32.u64 %0, t; }" : "=r"(a) : "l"(p));
    return a;
}

#if USE_TCGEN05
__device__ __forceinline__ uint32_t elect_one_pred() {
    uint32_t pred;
    asm volatile(
        "{\n\t.reg .pred p;\n\telect.sync _|p, 0xFFFFFFFF;\n\tselp.b32 %0, 1, 0, p;\n\t}"
        : "=r"(pred));
    return pred;
}

#define TCGEN05_ALLOC(smem_result_addr, nCols) \
    asm volatile("tcgen05.alloc.cta_group::1.sync.aligned.shared::cta.b32 [%0], %1;" \
        :: "r"((uint32_t)(smem_result_addr)), "r"((uint32_t)(nCols)) : "memory")
#define TCGEN05_DEALLOC(tmem_addr, nCols) \
    asm volatile("tcgen05.dealloc.cta_group::1.sync.aligned.b32 %0, %1;" \
        :: "r"(tmem_addr), "r"((uint32_t)(nCols)))
#define TCGEN05_RELINQUISH() \
    asm volatile("tcgen05.relinquish_alloc_permit.cta_group::1.sync.aligned;")
#define TCGEN05_COMMIT(mbar_smem_addr) \
    asm volatile("tcgen05.commit.cta_group::1.mbarrier::arrive::one.shared::cluster.b64 [%0];" \
        :: "r"((uint32_t)(mbar_smem_addr)) : "memory")
#define TCGEN05_FENCE_AFTER() \
    asm volatile("tcgen05.fence::after_thread_sync;" ::: "memory")
#define TCGEN05_WAIT_LD() \
    asm volatile("tcgen05.wait::ld.sync.aligned;" ::: "memory")
#define FENCE_PROXY_ASYNC_SHARED_CTA() \
    asm volatile("fence.proxy.async.shared::cta;" ::: "memory")
#define MBARRIER_INIT(mbar, count) \
    asm volatile("mbarrier.init.shared.b64 [%0], %1;" \
        :: "r"((uint32_t)(mbar)), "r"((uint32_t)(count)) : "memory")
#define MBARRIER_INVAL(mbar) \
    asm volatile("mbarrier.inval.shared.b64 [%0];" :: "r"((uint32_t)(mbar)) : "memory")

#define MBARRIER_WAIT_PARITY(mbar_smem_addr, phase_parity) do { \
    uint32_t _mbar = (uint32_t)(mbar_smem_addr); \
    uint32_t _parity = (uint32_t)(phase_parity); \
    uint32_t _done; \
    asm volatile( \
        "{\n\t.reg .pred p;\n\t" \
        "mbarrier.try_wait.parity.acquire.cta.shared::cta.b64 p, [%1], %2;\n\t" \
        "selp.b32 %0, 1, 0, p;\n\t}" \
        : "=r"(_done) : "r"(_mbar), "r"(_parity) : "memory"); \
    if (!_done) { \
        asm volatile( \
            "{\n\t.reg .pred P1;\n\t" \
            "WAIT_LOOP_%=:\n\t" \
            "mbarrier.try_wait.parity.acquire.cta.shared::cta.b64 P1, [%0], %1, 0x989680;\n\t" \
            "@P1 bra.uni WAIT_DONE_%=;\n\t" \
            "bra.uni WAIT_LOOP_%=;\n\t" \
            "WAIT_DONE_%=:\n\t}" \
            :: "r"(_mbar), "r"(_parity) : "memory"); \
    } \
} while(0)

#define TCGEN05_LD_32X32B_X32(r, tmem_addr) \
    asm volatile( \
        "tcgen05.ld.sync.aligned.32x32b.x32.b32 " \
        "{%0, %1, %2, %3, %4, %5, %6, %7, " \
        " %8, %9, %10, %11, %12, %13, %14, %15, " \
        " %16, %17, %18, %19, %20, %21, %22, %23, " \
        " %24, %25, %26, %27, %28, %29, %30, %31}, [%32];" \
        : "=r"((r)[0]),  "=r"((r)[1]),  "=r"((r)[2]),  "=r"((r)[3]), \
          "=r"((r)[4]),  "=r"((r)[5]),  "=r"((r)[6]),  "=r"((r)[7]), \
          "=r"((r)[8]),  "=r"((r)[9]),  "=r"((r)[10]), "=r"((r)[11]), \
          "=r"((r)[12]), "=r"((r)[13]), "=r"((r)[14]), "=r"((r)[15]), \
          "=r"((r)[16]), "=r"((r)[17]), "=r"((r)[18]), "=r"((r)[19]), \
          "=r"((r)[20]), "=r"((r)[21]), "=r"((r)[22]), "=r"((r)[23]), \
          "=r"((r)[24]), "=r"((r)[25]), "=r"((r)[26]), "=r"((r)[27]), \
          "=r"((r)[28]), "=r"((r)[29]), "=r"((r)[30]), "=r"((r)[31]) \
        : "r"(tmem_addr))

__device__ __forceinline__ void mma_f16_ss_cg1(
    uint32_t d_tmem, uint64_t a_desc, uint64_t b_desc, uint32_t idesc, bool en) {
    uint32_t e = en ? 1 : 0;
    asm volatile(
        "{\n\t.reg .pred p;\n\tsetp.ne.u32 p, %5, 0;\n\t"
        "tcgen05.mma.cta_group::1.kind::f16 [%0], %1, %2, %3, {%4, %4, %4, %4}, p;\n\t}"
        :: "r"(d_tmem), "l"(a_desc), "l"(b_desc), "r"(idesc), "r"(0u), "r"(e)
        : "memory");
}

static constexpr uint64_t SMEM_DESC_BASE_SW128 =
    (uint64_t(2) << 61) | (uint64_t(1) << 46) | (uint64_t(64) << 32) | (uint64_t(1) << 16);
#define MAKE_SMEM_DESC(base_addr) \
    (SMEM_DESC_BASE_SW128 | ((uint64_t)((base_addr) >> 4) & 0x3FFF))

// idesc: f32 accum, bf16 A/B, M=128, N=128
static constexpr uint32_t MMA_IDESC =
    (1u << 4) | (1u << 7) | (1u << 10) | ((128u / 8) << 17) | ((128u / 16) << 24);
#endif // USE_TCGEN05

// Fallback fragment ops (legal PTX at .target sm_103; runs on HMMA pipe)
__device__ __forceinline__ void ldmatrix_x4(uint32_t* r, uint32_t addr) {
    asm volatile("ldmatrix.sync.aligned.m8n8.x4.shared.b16 {%0,%1,%2,%3}, [%4];"
        : "=r"(r[0]), "=r"(r[1]), "=r"(r[2]), "=r"(r[3]) : "r"(addr));
}
__device__ __forceinline__ void mma_16816_bf16(float* c, const uint32_t* a, const uint32_t* b) {
    asm volatile(
        "mma.sync.aligned.m16n8k16.row.col.f32.bf16.bf16.f32 "
        "{%0,%1,%2,%3}, {%4,%5,%6,%7}, {%8,%9}, {%0,%1,%2,%3};"
        : "+f"(c[0]), "+f"(c[1]), "+f"(c[2]), "+f"(c[3])
        : "r"(a[0]), "r"(a[1]), "r"(a[2]), "r"(a[3]), "r"(b[0]), "r"(b[1]));
}

// ---------------------------------------------------------------------------
// Scratch (__device__ globals)
// ---------------------------------------------------------------------------
__device__ __align__(16) __nv_bfloat16 g_xb[N * D_O];
__device__ __align__(16) __nv_bfloat16 g_tb[N * D_T];
__device__ float g_sim_o[(size_t)N * N];
__device__ float g_sim_t[(size_t)N * N];
__device__ float g_dpart[2][N * NBJ];
__device__ float g_logden[2][N];
__device__ float g_losspart[2 * N];

// ---------------------------------------------------------------------------
// Row L2-normalize (fp32 math) -> bf16
// ---------------------------------------------------------------------------
__global__ void normalize_kernel(const float* __restrict__ x, int D, int which) {
    __nv_bfloat16* out = (which == 0) ? g_xb : g_tb;
    int row = blockIdx.x;
    const float* xr = x + (size_t)row * D;

    float ss = 0.f;
    for (int c = threadIdx.x; c < D; c += 256) {
        float v = xr[c];
        ss += v * v;
    }
    #pragma unroll
    for (int o = 16; o; o >>= 1) ss += __shfl_xor_sync(0xffffffffu, ss, o);

    __shared__ float sw[8];
    __shared__ float sscale;
    if ((threadIdx.x & 31) == 0) sw[threadIdx.x >> 5] = ss;
    __syncthreads();
    if (threadIdx.x == 0) {
        float t = 0.f;
        #pragma unroll
        for (int w = 0; w < 8; w++) t += sw[w];
        sscale = 1.0f / fmaxf(sqrtf(t), 1e-8f);
    }
    __syncthreads();

    float s = sscale;
    __nv_bfloat16* orow = out + (size_t)row * D;
    for (int c = threadIdx.x; c < D; c += 256) orow[c] = __float2bfloat16(xr[c] * s);
}

// ---------------------------------------------------------------------------
// Unified epilogue for one 128x64 half of the C tile, staged in SMEM.
//   - exp row-partials with diagonal excluded -> spart[r][h*2 + colhalf]
//   - coalesced store of sims to gmem
// ---------------------------------------------------------------------------
__device__ __forceinline__ void epilogue_half(
    const float* stage, float (*spart)[4], float* sim,
    int bi, int bj, int h, int tid)
{
    const int r  = tid >> 1;
    const int cp = tid & 1;
    const int gi  = bi * BM + r;
    const int gj0 = bj * BN + h * 64 + cp * 32;
    float es = 0.f;
    #pragma unroll
    for (int j = 0; j < 32; j++) {
        float v = stage[r * 65 + cp * 32 + j];
        if (gi != gj0 + j) es += expf(v);
    }
    spart[r][h * 2 + cp] = es;

    float* dst = sim + (size_t)(bi * BM) * N + (size_t)bj * BN + h * 64;
    #pragma unroll 4
    for (int p = 0; p < 32; p++) {
        int idx = p * 256 + tid;
        int rr = idx >> 6;
        int cc = idx & 63;
        dst[(size_t)rr * N + cc] = stage[rr * 65 + cc];
    }
}

// ---------------------------------------------------------------------------
// Tensor-core GEMM: sim = X @ X^T (128x128 tile per CTA) + exp partials.
// tcgen05 when the arch-specific pass exists; mma.sync fallback otherwise.
// ---------------------------------------------------------------------------
template <int WHICH>
__global__ void __launch_bounds__(256) gemm_tc_kernel() {
    constexpr int D   = (WHICH == 0) ? D_O : D_T;
    constexpr int NCH = D / 64;
    const __nv_bfloat16* X = (WHICH == 0) ? g_xb : g_tb;
    float* sim   = (WHICH == 0) ? g_sim_o : g_sim_t;
    float* dpart = g_dpart[WHICH];

    extern __shared__ char dsm_raw[];
    __shared__ float spart[128][4];

    const uint32_t raw  = smem_to_u32(dsm_raw);
    const uint32_t base = (raw + 1023u) & ~1023u;
    char* sm = dsm_raw + (base - raw);        // 1024-aligned
    const uint32_t smA = base;                // 16 KB: A chunk 128 x 64 bf16 SW128
    const uint32_t smB = base + 16384;        // 16 KB: B chunk
    float* stage = (float*)sm;                // reused post-K-loop: 128 x 65 fp32

    const int tid = threadIdx.x;
    const int wid = tid >> 5;
    const int lid = tid & 31;
    const int bi = blockIdx.y;
    const int bj = blockIdx.x;

    const __nv_bfloat16* Ab = X + (size_t)bi * BM * D;
    const __nv_bfloat16* Bb = X + (size_t)bj * BN * D;

#if USE_TCGEN05
    // ================= tcgen05 path =================
    __shared__ uint32_t s_tmem;
    __shared__ __align__(8) uint64_t s_mbar;

    if (wid == 0) {
        TCGEN05_ALLOC(smem_to_u32(&s_tmem), 128);
        TCGEN05_RELINQUISH();
    }
    if (tid == 0) MBARRIER_INIT(smem_to_u32(&s_mbar), 1);
    __syncthreads();
    const uint32_t tmem = s_tmem;
    const uint32_t mbar = smem_to_u32(&s_mbar);
    const uint64_t a_desc0 = MAKE_SMEM_DESC(smA);
    const uint64_t b_desc0 = MAKE_SMEM_DESC(smB);

    for (int c = 0; c < NCH; c++) {
        #pragma unroll
        for (int s = 0; s < 4; s++) {
            int seg = tid + s * 256;
            int row = seg >> 3;
            int sc  = seg & 7;
            uint4 va = *(const uint4*)(Ab + (size_t)row * D + c * 64 + sc * 8);
            uint4 vb = *(const uint4*)(Bb + (size_t)row * D + c * 64 + sc * 8);
            uint32_t off = SMEM_SWIZZLE_128B((uint32_t)(row * 128 + sc * 16));
            *(uint4*)(sm + off)         = va;
            *(uint4*)(sm + 16384 + off) = vb;
        }
        FENCE_PROXY_ASYNC_SHARED_CTA();
        __syncthreads();

        if (wid == 0 && elect_one_pred()) {
            #pragma unroll
            for (int k = 0; k < 4; k++) {
                mma_f16_ss_cg1(tmem, a_desc0 + k * 2, b_desc0 + k * 2,
                               MMA_IDESC, (c > 0) || (k > 0));
            }
            TCGEN05_COMMIT(mbar);
        }
        MBARRIER_WAIT_PARITY(mbar, c & 1);
        __syncthreads();
    }
    TCGEN05_FENCE_AFTER();

    const int sub = wid & 3;
    const int cg  = wid >> 2;
    const int r   = sub * 32 + lid;

    #pragma unroll
    for (int h = 0; h < 2; h++) {
        uint32_t dreg[32];
        TCGEN05_LD_32X32B_X32(dreg, tmem + h * 64 + cg * 32);
        TCGEN05_WAIT_LD();
        #pragma unroll
        for (int j = 0; j < 32; j++)
            stage[r * 65 + cg * 32 + j] = __uint_as_float(dreg[j]);
        __syncthreads();
        epilogue_half(stage, spart, sim, bi, bj, h, tid);
        __syncthreads();
    }

    if (tid == 0) MBARRIER_INVAL(mbar);
    __syncthreads();
    if (wid == 0) TCGEN05_DEALLOC(tmem, 128);
#else
    // ================= mma.sync fallback (HMMA) =================
    const int warp_m = wid & 3;   // 4 warps over M: 32 rows each
    const int warp_n = wid >> 2;  // 2 warps over N: 64 cols each

    float c[2][8][4];
    #pragma unroll
    for (int mt = 0; mt < 2; mt++)
        #pragma unroll
        for (int nt = 0; nt < 8; nt++)
            #pragma unroll
            for (int q = 0; q < 4; q++) c[mt][nt][q] = 0.f;

    for (int ch = 0; ch < NCH; ch++) {
        #pragma unroll
        for (int s = 0; s < 4; s++) {
            int seg = tid + s * 256;
            int row = seg >> 3;
            int sc  = seg & 7;
            uint4 va = *(const uint4*)(Ab + (size_t)row * D + ch * 64 + sc * 8);
            uint4 vb = *(const uint4*)(Bb + (size_t)row * D + ch * 64 + sc * 8);
            uint32_t off = SMEM_SWIZZLE_128B((uint32_t)(row * 128 + sc * 16));
            *(uint4*)(sm + off)         = va;
            *(uint4*)(sm + 16384 + off) = vb;
        }
        __syncthreads();

        #pragma unroll
        for (int ks = 0; ks < 4; ks++) {
            uint32_t a[2][4];
            #pragma unroll
            for (int mt = 0; mt < 2; mt++) {
                int row  = warp_m * 32 + mt * 16 + (lid & 15);
                int boff = ks * 32 + (lid >> 4) * 16;
                uint32_t addr = smA + SMEM_SWIZZLE_128B((uint32_t)(row * 128 + boff));
                ldmatrix_x4(a[mt], addr);
            }
            uint32_t b[8][2];
            #pragma unroll
            for (int np = 0; np < 4; np++) {
                int mat = lid >> 3;                 // 0..3
                int nt  = np * 2 + (mat >> 1);
                int kh  = mat & 1;
                int row  = warp_n * 64 + nt * 8 + (lid & 7);
                int boff = ks * 32 + kh * 16;
                uint32_t addr = smB + SMEM_SWIZZLE_128B((uint32_t)(row * 128 + boff));
                uint32_t r4[4];
                ldmatrix_x4(r4, addr);
                b[np * 2][0]     = r4[0];
                b[np * 2][1]     = r4[1];
                b[np * 2 + 1][0] = r4[2];
                b[np * 2 + 1][1] = r4[3];
            }
            #pragma unroll
            for (int mt = 0; mt < 2; mt++)
                #pragma unroll
                for (int nt = 0; nt < 8; nt++)
                    mma_16816_bf16(c[mt][nt], a[mt], b[nt]);
        }
        __syncthreads();
    }

    // Epilogue: stage one 128x64 half at a time (warp_n == h owns it)
    #pragma unroll
    for (int h = 0; h < 2; h++) {
        if (warp_n == h) {
            #pragma unroll
            for (int mt = 0; mt < 2; mt++)
                #pragma unroll
                for (int nt = 0; nt < 8; nt++) {
                    int r0  = warp_m * 32 + mt * 16 + (lid >> 2);
                    int col = nt * 8 + (lid & 3) * 2;
                    stage[r0 * 65 + col]           = c[mt][nt][0];
                    stage[r0 * 65 + col + 1]       = c[mt][nt][1];
                    stage[(r0 + 8) * 65 + col]     = c[mt][nt][2];
                    stage[(r0 + 8) * 65 + col + 1] = c[mt][nt][3];
                }
        }
        __syncthreads();
        epilogue_half(stage, spart, sim, bi, bj, h, tid);
        __syncthreads();
    }
#endif

    if (tid < 128) {
        float t = spart[tid][0] + spart[tid][1] + spart[tid][2] + spart[tid][3];
        dpart[(bi * BM + tid) * NBJ + bj] = t;
    }
}

// ---------------------------------------------------------------------------
// Per-row log-denominator
// ---------------------------------------------------------------------------
__global__ void logdenom_kernel(int which) {
    const float* dpart = g_dpart[which];
    float* ld = g_logden[which];
    int row = blockIdx.x;
    float v = dpart[row * NBJ + threadIdx.x];
    #pragma unroll
    for (int o = 16; o; o >>= 1) v += __shfl_xor_sync(0xffffffffu, v, o);
    __shared__ float sw[2];
    if ((threadIdx.x & 31) == 0) sw[threadIdx.x >> 5] = v;
    __syncthreads();
    if (threadIdx.x == 0) ld[row] = logf(sw[0] + sw[1]);
}

// ---------------------------------------------------------------------------
// Loss pass
// ---------------------------------------------------------------------------
__global__ void loss_kernel() {
    const int b  = blockIdx.x;
    const int i  = b >> 1;
    const int j0 = (b & 1) * (N / 2);
    const float Lo = g_logden[0][i];
    const float Lt = g_logden[1][i];
    const float* so = g_sim_o + (size_t)i * N + j0;
    const float* st = g_sim_t + (size_t)i * N + j0;

    float acc = 0.f;
    for (int k = threadIdx.x; k < N / 2; k += 256) {
        if (j0 + k == i) continue;
        float s_t = st[k];
        float s_o = so[k];
        float ltp = s_t - Lt;
        float tp  = expf(ltp);
        acc += tp * tp * tp * (ltp - (s_o - Lo));
    }
    #pragma unroll
    for (int o = 16; o; o >>= 1) acc += __shfl_xor_sync(0xffffffffu, acc, o);
    __shared__ float sw[8];
    if ((threadIdx.x & 31) == 0) sw[threadIdx.x >> 5] = acc;
    __syncthreads();
    if (threadIdx.x == 0) {
        float t = 0.f;
        #pragma unroll
        for (int w = 0; w < 8; w++) t += sw[w];
        g_losspart[b] = t;
    }
}

__global__ void final_kernel(float* out) {
    float acc = 0.f;
    for (int k = threadIdx.x; k < 2 * N; k += 256) acc += g_losspart[k];
    #pragma unroll
    for (int o = 16; o; o >>= 1) acc += __shfl_xor_sync(0xffffffffu, acc, o);
    __shared__ float sw[8];
    if ((threadIdx.x & 31) == 0) sw[threadIdx.x >> 5] = acc;
    __syncthreads();
    if (threadIdx.x == 0) {
        float t = 0.f;
        #pragma unroll
        for (int w = 0; w < 8; w++) t += sw[w];
        out[0] = t * (1.0f / ((float)N * (float)N));
    }
}

// ---------------------------------------------------------------------------
// Launch (graph-capturable)
// ---------------------------------------------------------------------------
extern "C" void kernel_launch(void* const* d_in, const int* in_sizes, int n_in,
                              void* d_out, int out_size) {
    const float* mo = (const float*)d_in[0];
    const float* tg = (const float*)d_in[1];
    float* out = (float*)d_out;

    normalize_kernel<<<N, 256>>>(mo, D_O, 0);
    normalize_kernel<<<N, 256>>>(tg, D_T, 1);

    dim3 grid(NBJ, N / BM);  // 64 x 64
    const int dsm = 128 * 65 * 4 + 1024;   // stage region (>= 32KB chunk buffers)
    gemm_tc_kernel<0><<<grid, 256, dsm>>>();
    gemm_tc_kernel<1><<<grid, 256, dsm>>>();

    logdenom_kernel<<<N, 64>>>(0);
    logdenom_kernel<<<N, 64>>>(1);

    loss_kernel<<<2 * N, 256>>>();
    final_kernel<<<1, 256>>>(out);
}

// round 4
// speedup vs baseline: 12.5718x; 1.7523x over previous
#include <cuda_runtime.h>
#include <cuda_bf16.h>
#include <math.h>
#include <stdint.h>

// Problem constants
#define N    8192
#define D_O  512
#define D_T  768

#define BM 128
#define BN 128
#define NBJ (N / BN)                 // 64 column-blocks
#define NT  (NBJ * (NBJ + 1) / 2)    // 2080 upper-tri tiles

// Arch-specific (sm_103a) feature gate: tcgen05 PTX only legal at compute_103a.
#if defined(__CUDA_ARCH__) && defined(__CUDA_ARCH_FEAT_SM103_ALL)
#define USE_TCGEN05 1
#else
#define USE_TCGEN05 0
#endif

#define SMEM_SWIZZLE_128B(b) ((b) ^ (((b) >> 3) & 0x70))

// ---------------------------------------------------------------------------
// Common helpers
// ---------------------------------------------------------------------------
__device__ __forceinline__ uint32_t smem_to_u32(const void* p) {
    uint32_t a;
    asm("{ .reg .u64 t; cvta.to.shared.u64 t, %1; cvt.u32.u64 %0, t; }" : "=r"(a) : "l"(p));
    return a;
}

#define CP_ASYNC16(sa, ga) \
    asm volatile("cp.async.cg.shared.global [%0], [%1], 16;" :: "r"(sa), "l"(ga))
#define CP_COMMIT() asm volatile("cp.async.commit_group;" ::: "memory")
#define CP_WAIT(n)  asm volatile("cp.async.wait_group %0;" :: "n"(n) : "memory")

#if USE_TCGEN05
__device__ __forceinline__ uint32_t elect_one_pred() {
    uint32_t pred;
    asm volatile(
        "{\n\t.reg .pred p;\n\telect.sync _|p, 0xFFFFFFFF;\n\tselp.b32 %0, 1, 0, p;\n\t}"
        : "=r"(pred));
    return pred;
}

#define TCGEN05_ALLOC(smem_result_addr, nCols) \
    asm volatile("tcgen05.alloc.cta_group::1.sync.aligned.shared::cta.b32 [%0], %1;" \
        :: "r"((uint32_t)(smem_result_addr)), "r"((uint32_t)(nCols)) : "memory")
#define TCGEN05_DEALLOC(tmem_addr, nCols) \
    asm volatile("tcgen05.dealloc.cta_group::1.sync.aligned.b32 %0, %1;" \
        :: "r"(tmem_addr), "r"((uint32_t)(nCols)))
#define TCGEN05_RELINQUISH() \
    asm volatile("tcgen05.relinquish_alloc_permit.cta_group::1.sync.aligned;")
#define TCGEN05_COMMIT(mbar_smem_addr) \
    asm volatile("tcgen05.commit.cta_group::1.mbarrier::arrive::one.shared::cluster.b64 [%0];" \
        :: "r"((uint32_t)(mbar_smem_addr)) : "memory")
#define TCGEN05_FENCE_AFTER() \
    asm volatile("tcgen05.fence::after_thread_sync;" ::: "memory")
#define TCGEN05_WAIT_LD() \
    asm volatile("tcgen05.wait::ld.sync.aligned;" ::: "memory")
#define FENCE_PROXY_ASYNC_SHARED_CTA() \
    asm volatile("fence.proxy.async.shared::cta;" ::: "memory")
#define MBARRIER_INIT(mbar, count) \
    asm volatile("mbarrier.init.shared.b64 [%0], %1;" \
        :: "r"((uint32_t)(mbar)), "r"((uint32_t)(count)) : "memory")
#define MBARRIER_INVAL(mbar) \
    asm volatile("mbarrier.inval.shared.b64 [%0];" :: "r"((uint32_t)(mbar)) : "memory")

#define MBARRIER_WAIT_PARITY(mbar_smem_addr, phase_parity) do { \
    uint32_t _mbar = (uint32_t)(mbar_smem_addr); \
    uint32_t _parity = (uint32_t)(phase_parity); \
    uint32_t _done; \
    asm volatile( \
        "{\n\t.reg .pred p;\n\t" \
        "mbarrier.try_wait.parity.acquire.cta.shared::cta.b64 p, [%1], %2;\n\t" \
        "selp.b32 %0, 1, 0, p;\n\t}" \
        : "=r"(_done) : "r"(_mbar), "r"(_parity) : "memory"); \
    if (!_done) { \
        asm volatile( \
            "{\n\t.reg .pred P1;\n\t" \
            "WAIT_LOOP_%=:\n\t" \
            "mbarrier.try_wait.parity.acquire.cta.shared::cta.b64 P1, [%0], %1, 0x989680;\n\t" \
            "@P1 bra.uni WAIT_DONE_%=;\n\t" \
            "bra.uni WAIT_LOOP_%=;\n\t" \
            "WAIT_DONE_%=:\n\t}" \
            :: "r"(_mbar), "r"(_parity) : "memory"); \
    } \
} while(0)

#define TCGEN05_LD_32X32B_X32(r, tmem_addr) \
    asm volatile( \
        "tcgen05.ld.sync.aligned.32x32b.x32.b32 " \
        "{%0, %1, %2, %3, %4, %5, %6, %7, " \
        " %8, %9, %10, %11, %12, %13, %14, %15, " \
        " %16, %17, %18, %19, %20, %21, %22, %23, " \
        " %24, %25, %26, %27, %28, %29, %30, %31}, [%32];" \
        : "=r"((r)[0]),  "=r"((r)[1]),  "=r"((r)[2]),  "=r"((r)[3]), \
          "=r"((r)[4]),  "=r"((r)[5]),  "=r"((r)[6]),  "=r"((r)[7]), \
          "=r"((r)[8]),  "=r"((r)[9]),  "=r"((r)[10]), "=r"((r)[11]), \
          "=r"((r)[12]), "=r"((r)[13]), "=r"((r)[14]), "=r"((r)[15]), \
          "=r"((r)[16]), "=r"((r)[17]), "=r"((r)[18]), "=r"((r)[19]), \
          "=r"((r)[20]), "=r"((r)[21]), "=r"((r)[22]), "=r"((r)[23]), \
          "=r"((r)[24]), "=r"((r)[25]), "=r"((r)[26]), "=r"((r)[27]), \
          "=r"((r)[28]), "=r"((r)[29]), "=r"((r)[30]), "=r"((r)[31]) \
        : "r"(tmem_addr))

__device__ __forceinline__ void mma_f16_ss_cg1(
    uint32_t d_tmem, uint64_t a_desc, uint64_t b_desc, uint32_t idesc, bool en) {
    uint32_t e = en ? 1 : 0;
    asm volatile(
        "{\n\t.reg .pred p;\n\tsetp.ne.u32 p, %5, 0;\n\t"
        "tcgen05.mma.cta_group::1.kind::f16 [%0], %1, %2, %3, {%4, %4, %4, %4}, p;\n\t}"
        :: "r"(d_tmem), "l"(a_desc), "l"(b_desc), "r"(idesc), "r"(0u), "r"(e)
        : "memory");
}

static constexpr uint64_t SMEM_DESC_BASE_SW128 =
    (uint64_t(2) << 61) | (uint64_t(1) << 46) | (uint64_t(64) << 32) | (uint64_t(1) << 16);
#define MAKE_SMEM_DESC(base_addr) \
    (SMEM_DESC_BASE_SW128 | ((uint64_t)((base_addr) >> 4) & 0x3FFF))

// idesc: f32 accum, bf16 A/B, M=128, N=128
static constexpr uint32_t MMA_IDESC =
    (1u << 4) | (1u << 7) | (1u << 10) | ((128u / 8) << 17) | ((128u / 16) << 24);
#endif // USE_TCGEN05

// Fallback fragment ops (legal PTX at .target sm_103; compile-only safety net)
__device__ __forceinline__ void ldmatrix_x4(uint32_t* r, uint32_t addr) {
    asm volatile("ldmatrix.sync.aligned.m8n8.x4.shared.b16 {%0,%1,%2,%3}, [%4];"
        : "=r"(r[0]), "=r"(r[1]), "=r"(r[2]), "=r"(r[3]) : "r"(addr));
}
__device__ __forceinline__ void mma_16816_bf16(float* c, const uint32_t* a, const uint32_t* b) {
    asm volatile(
        "mma.sync.aligned.m16n8k16.row.col.f32.bf16.bf16.f32 "
        "{%0,%1,%2,%3}, {%4,%5,%6,%7}, {%8,%9}, {%0,%1,%2,%3};"
        : "+f"(c[0]), "+f"(c[1]), "+f"(c[2]), "+f"(c[3])
        : "r"(a[0]), "r"(a[1]), "r"(a[2]), "r"(a[3]), "r"(b[0]), "r"(b[1]));
}

// ---------------------------------------------------------------------------
// Scratch (__device__ globals)
// ---------------------------------------------------------------------------
__device__ __align__(16) __nv_bfloat16 g_xb[N * D_O];
__device__ __align__(16) __nv_bfloat16 g_tb[N * D_T];
__device__ __align__(16) __nv_bfloat16 g_simb_o[(size_t)N * N];   // 128 MB
__device__ __align__(16) __nv_bfloat16 g_simb_t[(size_t)N * N];   // 128 MB
__device__ float g_dpart[2][N * NBJ];
__device__ float g_logden[2][N];
__device__ float g_losspart[2 * N];

// ---------------------------------------------------------------------------
// Row L2-normalize (fp32 math) -> bf16
// ---------------------------------------------------------------------------
__global__ void normalize_kernel(const float* __restrict__ x, int D, int which) {
    __nv_bfloat16* out = (which == 0) ? g_xb : g_tb;
    int row = blockIdx.x;
    const float* xr = x + (size_t)row * D;

    float ss = 0.f;
    for (int c = threadIdx.x; c < D; c += 256) {
        float v = xr[c];
        ss += v * v;
    }
    #pragma unroll
    for (int o = 16; o; o >>= 1) ss += __shfl_xor_sync(0xffffffffu, ss, o);

    __shared__ float sw[8];
    __shared__ float sscale;
    if ((threadIdx.x & 31) == 0) sw[threadIdx.x >> 5] = ss;
    __syncthreads();
    if (threadIdx.x == 0) {
        float t = 0.f;
        #pragma unroll
        for (int w = 0; w < 8; w++) t += sw[w];
        sscale = 1.0f / fmaxf(sqrtf(t), 1e-8f);
    }
    __syncthreads();

    float s = sscale;
    __nv_bfloat16* orow = out + (size_t)row * D;
    for (int c = threadIdx.x; c < D; c += 256) orow[c] = __float2bfloat16(xr[c] * s);
}

// ---------------------------------------------------------------------------
// cp.async chunk loader: 128 rows x 64 bf16 for A and B, SW128-swizzled.
// ---------------------------------------------------------------------------
__device__ __forceinline__ void load_chunk(
    const __nv_bfloat16* Ab, const __nv_bfloat16* Bb, int D, int c,
    uint32_t smA, uint32_t smB, int tid)
{
    #pragma unroll
    for (int s = 0; s < 4; s++) {
        int seg = tid + s * 256;
        int row = seg >> 3;
        int sc  = seg & 7;
        uint32_t off = SMEM_SWIZZLE_128B((uint32_t)(row * 128 + sc * 16));
        CP_ASYNC16(smA + off, Ab + (size_t)row * D + c * 64 + sc * 8);
        CP_ASYNC16(smB + off, Bb + (size_t)row * D + c * 64 + sc * 8);
    }
}

// ---------------------------------------------------------------------------
// Symmetric epilogue for one 128x64 half of the C tile (staged fp32 in SMEM):
//  - row exp-partials (diag excluded) -> spart
//  - col exp-partials (off-diag)      -> dpart for the bj block
//  - bf16 stores of tile (bi,bj) and its transpose (bj,bi)
// ---------------------------------------------------------------------------
__device__ __forceinline__ void epilogue_half_sym(
    const float* stage, float (*spart)[4], float (*scolp)[4],
    __nv_bfloat16* simb, float* dpart, int bi, int bj, int h, int tid)
{
    // Row partials
    {
        const int r  = tid >> 1;
        const int cp = tid & 1;
        const int gi  = bi * BM + r;
        const int gj0 = bj * BN + h * 64 + cp * 32;
        float es = 0.f;
        #pragma unroll
        for (int j = 0; j < 32; j++) {
            float v = stage[r * 65 + cp * 32 + j];
            if (gi != gj0 + j) es += __expf(v);
        }
        spart[r][h * 2 + cp] = es;
    }

    // Col partials (only needed off-diagonal)
    if (bi != bj) {
        const int cc   = tid & 63;
        const int part = tid >> 6;
        float ec = 0.f;
        #pragma unroll
        for (int rr = 0; rr < 32; rr++)
            ec += __expf(stage[(part * 32 + rr) * 65 + cc]);
        scolp[cc][part] = ec;
    }

    // Store tile (bi,bj) half h: 128 rows x 64 cols, bf16 pairs, coalesced
    {
        __nv_bfloat16* dst = simb + (size_t)(bi * BM) * N + (size_t)bj * BN + h * 64;
        #pragma unroll
        for (int p = 0; p < 16; p++) {
            int pidx = p * 256 + tid;          // 4096 pairs
            int rr = pidx >> 5;                // 32 pairs per row
            int c2 = (pidx & 31) * 2;
            __nv_bfloat162 v;
            v.x = __float2bfloat16(stage[rr * 65 + c2]);
            v.y = __float2bfloat16(stage[rr * 65 + c2 + 1]);
            *(__nv_bfloat162*)(dst + (size_t)rr * N + c2) = v;
        }
    }

    // Store transposed tile (bj,bi): 64 rows x 128 cols
    if (bi != bj) {
        __nv_bfloat16* dst2 = simb + (size_t)(bj * BN + h * 64) * N + (size_t)bi * BM;
        #pragma unroll
        for (int p = 0; p < 16; p++) {
            int pidx = p * 256 + tid;          // 4096 pairs: 64 rows x 64 pairs
            int rr2 = pidx >> 6;
            int c2  = (pidx & 63) * 2;
            __nv_bfloat162 v;
            v.x = __float2bfloat16(stage[c2 * 65 + rr2]);
            v.y = __float2bfloat16(stage[(c2 + 1) * 65 + rr2]);
            *(__nv_bfloat162*)(dst2 + (size_t)rr2 * N + c2) = v;
        }
    }

    __syncthreads();
    if (bi != bj && tid < 64) {
        float t = scolp[tid][0] + scolp[tid][1] + scolp[tid][2] + scolp[tid][3];
        dpart[(size_t)(bj * BN + h * 64 + tid) * NBJ + bi] = t;
    }
}

// ---------------------------------------------------------------------------
// Tensor-core GEMM on upper-tri tiles: sim tile (bi,bj) + transpose + partials
// ---------------------------------------------------------------------------
template <int WHICH>
__global__ void __launch_bounds__(256) gemm_tc_kernel() {
    constexpr int D   = (WHICH == 0) ? D_O : D_T;
    constexpr int NCH = D / 64;
    const __nv_bfloat16* X = (WHICH == 0) ? g_xb : g_tb;
    __nv_bfloat16* simb = (WHICH == 0) ? g_simb_o : g_simb_t;
    float* dpart = g_dpart[WHICH];

    extern __shared__ char dsm_raw[];
    __shared__ float spart[128][4];
    __shared__ float scolp[64][4];

    const uint32_t raw  = smem_to_u32(dsm_raw);
    const uint32_t base = (raw + 1023u) & ~1023u;
    char* sm = dsm_raw + (base - raw);        // 1024-aligned; 96 KB = 3 stages
    float* stage = (float*)sm;                // reused post-K-loop: 128 x 65 fp32

    const int tid = threadIdx.x;
    const int wid = tid >> 5;
    const int lid = tid & 31;

    // Triangular decode: blockIdx.x -> (bi, bj), bi <= bj
    int t = blockIdx.x;
    int bi = (int)(NBJ + 0.5f - sqrtf((NBJ + 0.5f) * (NBJ + 0.5f) - 2.0f * (float)t));
    if (bi < 0) bi = 0;
    if (bi > NBJ - 1) bi = NBJ - 1;
    #define TRI_START(x) ((x) * (2 * NBJ - (x) + 1) / 2)
    while (bi > 0 && TRI_START(bi) > t) bi--;
    while (bi < NBJ - 1 && TRI_START(bi + 1) <= t) bi++;
    const int bj = bi + (t - TRI_START(bi));
    #undef TRI_START

    const __nv_bfloat16* Ab = X + (size_t)bi * BM * D;
    const __nv_bfloat16* Bb = X + (size_t)bj * BN * D;

#if USE_TCGEN05
    // ================= tcgen05 path: 3-stage cp.async pipeline =================
    __shared__ uint32_t s_tmem;
    __shared__ __align__(8) uint64_t s_mbar[3];

    if (wid == 0) {
        TCGEN05_ALLOC(smem_to_u32(&s_tmem), 128);
        TCGEN05_RELINQUISH();
    }
    if (tid == 0) {
        MBARRIER_INIT(smem_to_u32(&s_mbar[0]), 1);
        MBARRIER_INIT(smem_to_u32(&s_mbar[1]), 1);
        MBARRIER_INIT(smem_to_u32(&s_mbar[2]), 1);
    }
    __syncthreads();
    const uint32_t tmem = s_tmem;

    // 3 buffers of 32 KB (A 16K + B 16K each)
    uint32_t smA[3], smB[3];
    uint64_t adesc[3], bdesc[3];
    #pragma unroll
    for (int s = 0; s < 3; s++) {
        smA[s] = base + s * 32768u;
        smB[s] = smA[s] + 16384u;
        adesc[s] = MAKE_SMEM_DESC(smA[s]);
        bdesc[s] = MAKE_SMEM_DESC(smB[s]);
    }

    load_chunk(Ab, Bb, D, 0, smA[0], smB[0], tid); CP_COMMIT();
    load_chunk(Ab, Bb, D, 1, smA[1], smB[1], tid); CP_COMMIT();
    load_chunk(Ab, Bb, D, 2, smA[2], smB[2], tid); CP_COMMIT();

    for (int c = 0; c < NCH; c++) {
        const int b = c % 3;
        if (c + 2 < NCH)      CP_WAIT(2);
        else if (c + 1 < NCH) CP_WAIT(1);
        else                  CP_WAIT(0);
        FENCE_PROXY_ASYNC_SHARED_CTA();
        __syncthreads();

        if (wid == 0 && elect_one_pred()) {
            #pragma unroll
            for (int k = 0; k < 4; k++)
                mma_f16_ss_cg1(tmem, adesc[b] + k * 2, bdesc[b] + k * 2,
                               MMA_IDESC, (c > 0) || (k > 0));
            TCGEN05_COMMIT(smem_to_u32(&s_mbar[b]));
        }
        if (c + 3 < NCH) {
            MBARRIER_WAIT_PARITY(smem_to_u32(&s_mbar[b]), (c / 3) & 1);
            load_chunk(Ab, Bb, D, c + 3, smA[b], smB[b], tid); CP_COMMIT();
        }
    }
    MBARRIER_WAIT_PARITY(smem_to_u32(&s_mbar[(NCH - 1) % 3]), ((NCH - 1) / 3) & 1);
    TCGEN05_FENCE_AFTER();
    __syncthreads();

    const int sub = wid & 3;
    const int cg  = wid >> 2;
    const int r   = sub * 32 + lid;

    #pragma unroll
    for (int h = 0; h < 2; h++) {
        uint32_t dreg[32];
        TCGEN05_LD_32X32B_X32(dreg, tmem + h * 64 + cg * 32);
        TCGEN05_WAIT_LD();
        #pragma unroll
        for (int j = 0; j < 32; j++)
            stage[r * 65 + cg * 32 + j] = __uint_as_float(dreg[j]);
        __syncthreads();
        epilogue_half_sym(stage, spart, scolp, simb, dpart, bi, bj, h, tid);
        __syncthreads();
    }

    if (tid == 0) {
        MBARRIER_INVAL(smem_to_u32(&s_mbar[0]));
        MBARRIER_INVAL(smem_to_u32(&s_mbar[1]));
        MBARRIER_INVAL(smem_to_u32(&s_mbar[2]));
    }
    __syncthreads();
    if (wid == 0) TCGEN05_DEALLOC(tmem, 128);
#else
    // ================= mma.sync fallback (compile-only safety net) =============
    const uint32_t smA0 = base;
    const uint32_t smB0 = base + 16384u;
    char* smc = sm;
    const int warp_m = wid & 3;
    const int warp_n = wid >> 2;

    float c[2][8][4];
    #pragma unroll
    for (int mt = 0; mt < 2; mt++)
        #pragma unroll
        for (int nt = 0; nt < 8; nt++)
            #pragma unroll
            for (int q = 0; q < 4; q++) c[mt][nt][q] = 0.f;

    for (int ch = 0; ch < NCH; ch++) {
        #pragma unroll
        for (int s = 0; s < 4; s++) {
            int seg = tid + s * 256;
            int row = seg >> 3;
            int sc  = seg & 7;
            uint4 va = *(const uint4*)(Ab + (size_t)row * D + ch * 64 + sc * 8);
            uint4 vb = *(const uint4*)(Bb + (size_t)row * D + ch * 64 + sc * 8);
            uint32_t off = SMEM_SWIZZLE_128B((uint32_t)(row * 128 + sc * 16));
            *(uint4*)(smc + off)         = va;
            *(uint4*)(smc + 16384 + off) = vb;
        }
        __syncthreads();

        #pragma unroll
        for (int ks = 0; ks < 4; ks++) {
            uint32_t a[2][4];
            #pragma unroll
            for (int mt = 0; mt < 2; mt++) {
                int row  = warp_m * 32 + mt * 16 + (lid & 15);
                int boff = ks * 32 + (lid >> 4) * 16;
                ldmatrix_x4(a[mt], smA0 + SMEM_SWIZZLE_128B((uint32_t)(row * 128 + boff)));
            }
            uint32_t b[8][2];
            #pragma unroll
            for (int np = 0; np < 4; np++) {
                int mat = lid >> 3;
                int nt  = np * 2 + (mat >> 1);
                int kh  = mat & 1;
                int row  = warp_n * 64 + nt * 8 + (lid & 7);
                int boff = ks * 32 + kh * 16;
                uint32_t r4[4];
                ldmatrix_x4(r4, smB0 + SMEM_SWIZZLE_128B((uint32_t)(row * 128 + boff)));
                b[np * 2][0]     = r4[0];
                b[np * 2][1]     = r4[1];
                b[np * 2 + 1][0] = r4[2];
                b[np * 2 + 1][1] = r4[3];
            }
            #pragma unroll
            for (int mt = 0; mt < 2; mt++)
                #pragma unroll
                for (int nt = 0; nt < 8; nt++)
                    mma_16816_bf16(c[mt][nt], a[mt], b[nt]);
        }
        __syncthreads();
    }

    #pragma unroll
    for (int h = 0; h < 2; h++) {
        if (warp_n == h) {
            #pragma unroll
            for (int mt = 0; mt < 2; mt++)
                #pragma unroll
                for (int nt = 0; nt < 8; nt++) {
                    int r0  = warp_m * 32 + mt * 16 + (lid >> 2);
                    int col = nt * 8 + (lid & 3) * 2;
                    stage[r0 * 65 + col]           = c[mt][nt][0];
                    stage[r0 * 65 + col + 1]       = c[mt][nt][1];
                    stage[(r0 + 8) * 65 + col]     = c[mt][nt][2];
                    stage[(r0 + 8) * 65 + col + 1] = c[mt][nt][3];
                }
        }
        __syncthreads();
        epilogue_half_sym(stage, spart, scolp, simb, dpart, bi, bj, h, tid);
        __syncthreads();
    }
#endif

    if (tid < 128) {
        float t2 = spart[tid][0] + spart[tid][1] + spart[tid][2] + spart[tid][3];
        dpart[(size_t)(bi * BM + tid) * NBJ + bj] = t2;
    }
}

// ---------------------------------------------------------------------------
// Per-row log-denominator
// ---------------------------------------------------------------------------
__global__ void logdenom_kernel(int which) {
    const float* dpart = g_dpart[which];
    float* ld = g_logden[which];
    int row = blockIdx.x;
    float v = dpart[(size_t)row * NBJ + threadIdx.x];
    #pragma unroll
    for (int o = 16; o; o >>= 1) v += __shfl_xor_sync(0xffffffffu, v, o);
    __shared__ float sw[2];
    if ((threadIdx.x & 31) == 0) sw[threadIdx.x >> 5] = v;
    __syncthreads();
    if (threadIdx.x == 0) ld[row] = logf(sw[0] + sw[1]);
}

// ---------------------------------------------------------------------------
// Loss pass over bf16 sims
// ---------------------------------------------------------------------------
__global__ void loss_kernel() {
    const int b  = blockIdx.x;
    const int i  = b >> 1;
    const int j0 = (b & 1) * (N / 2);
    const float Lo = g_logden[0][i];
    const float Lt = g_logden[1][i];
    const __nv_bfloat16* so = g_simb_o + (size_t)i * N + j0;
    const __nv_bfloat16* st = g_simb_t + (size_t)i * N + j0;

    float acc = 0.f;
    for (int k2 = threadIdx.x; k2 < N / 4; k2 += 256) {   // pairs
        int k = k2 * 2;
        __nv_bfloat162 vt = *(const __nv_bfloat162*)(st + k);
        __nv_bfloat162 vo = *(const __nv_bfloat162*)(so + k);
        #pragma unroll
        for (int u = 0; u < 2; u++) {
            if (j0 + k + u == i) continue;
            float s_t = (u == 0) ? __bfloat162float(vt.x) : __bfloat162float(vt.y);
            float s_o = (u == 0) ? __bfloat162float(vo.x) : __bfloat162float(vo.y);
            float ltp = s_t - Lt;
            float tp  = __expf(ltp);
            acc += tp * tp * tp * (ltp - (s_o - Lo));
        }
    }
    #pragma unroll
    for (int o = 16; o; o >>= 1) acc += __shfl_xor_sync(0xffffffffu, acc, o);
    __shared__ float sw[8];
    if ((threadIdx.x & 31) == 0) sw[threadIdx.x >> 5] = acc;
    __syncthreads();
    if (threadIdx.x == 0) {
        float t = 0.f;
        #pragma unroll
        for (int w = 0; w < 8; w++) t += sw[w];
        g_losspart[b] = t;
    }
}

__global__ void final_kernel(float* out) {
    float acc = 0.f;
    for (int k = threadIdx.x; k < 2 * N; k += 256) acc += g_losspart[k];
    #pragma unroll
    for (int o = 16; o; o >>= 1) acc += __shfl_xor_sync(0xffffffffu, acc, o);
    __shared__ float sw[8];
    if ((threadIdx.x & 31) == 0) sw[threadIdx.x >> 5] = acc;
    __syncthreads();
    if (threadIdx.x == 0) {
        float t = 0.f;
        #pragma unroll
        for (int w = 0; w < 8; w++) t += sw[w];
        out[0] = t * (1.0f / ((float)N * (float)N));
    }
}

// ---------------------------------------------------------------------------
// Launch (graph-capturable)
// ---------------------------------------------------------------------------
extern "C" void kernel_launch(void* const* d_in, const int* in_sizes, int n_in,
                              void* d_out, int out_size) {
    const float* mo = (const float*)d_in[0];
    const float* tg = (const float*)d_in[1];
    float* out = (float*)d_out;

    const int dsm = 3 * 32768 + 1024;   // 3-stage buffers + align slack (stage overlays)
    cudaFuncSetAttribute(gemm_tc_kernel<0>, cudaFuncAttributeMaxDynamicSharedMemorySize, dsm);
    cudaFuncSetAttribute(gemm_tc_kernel<1>, cudaFuncAttributeMaxDynamicSharedMemorySize, dsm);

    normalize_kernel<<<N, 256>>>(mo, D_O, 0);
    normalize_kernel<<<N, 256>>>(tg, D_T, 1);

    gemm_tc_kernel<0><<<NT, 256, dsm>>>();
    gemm_tc_kernel<1><<<NT, 256, dsm>>>();

    logdenom_kernel<<<N, 64>>>(0);
    logdenom_kernel<<<N, 64>>>(1);

    loss_kernel<<<2 * N, 256>>>();
    final_kernel<<<1, 256>>>(out);
}